// round 1
// baseline (speedup 1.0000x reference)
#include <cuda_runtime.h>
#include <cuda_bf16.h>

#define TT 512
#define BB 32
#define VV 8000
#define LL 100
#define SS (2*LL+1)   // 201
#define NEGF (-1e30f)

// Scratch (allocation-free rule: __device__ globals)
__device__ float g_logZ[TT*BB];
__device__ float g_lp[TT*BB*SS];      // 13.2 MB
__device__ float g_ps[BB];

__device__ __forceinline__ float logadd2(float a, float b) {
    float m = fmaxf(a, b);
    float d = fminf(a, b) - m;        // <= 0
    return m + log1pf(__expf(d));
}

// ---------------------------------------------------------------------------
// K1: logZ[t,b] = logsumexp over V of acts[t,b,:]  (one block per row)
// ---------------------------------------------------------------------------
__global__ __launch_bounds__(256) void logz_kernel(const float* __restrict__ acts) {
    const int row = blockIdx.x;                    // t*BB + b
    const float4* __restrict__ p = (const float4*)(acts + (size_t)row * VV);
    const int tid = threadIdx.x;

    float m = NEGF, s = 0.f;
    #pragma unroll 4
    for (int i = tid; i < VV/4; i += 256) {
        float4 v = p[i];
        float mx = fmaxf(fmaxf(v.x, v.y), fmaxf(v.z, v.w));
        if (mx > m) { s *= __expf(m - mx); m = mx; }
        s += __expf(v.x - m) + __expf(v.y - m) + __expf(v.z - m) + __expf(v.w - m);
    }
    // warp reduce (m,s)
    #pragma unroll
    for (int off = 16; off; off >>= 1) {
        float m2 = __shfl_xor_sync(0xffffffffu, m, off);
        float s2 = __shfl_xor_sync(0xffffffffu, s, off);
        float M = fmaxf(m, m2);
        s = s * __expf(m - M) + s2 * __expf(m2 - M);
        m = M;
    }
    __shared__ float sm[8], ss[8];
    int w = tid >> 5;
    if ((tid & 31) == 0) { sm[w] = m; ss[w] = s; }
    __syncthreads();
    if (tid == 0) {
        float M = sm[0], Sv = ss[0];
        #pragma unroll
        for (int i = 1; i < 8; i++) {
            float m2 = sm[i], s2 = ss[i];
            float Mn = fmaxf(M, m2);
            Sv = Sv * __expf(M - Mn) + s2 * __expf(m2 - Mn);
            M = Mn;
        }
        g_logZ[row] = M + __logf(Sv);
    }
}

// ---------------------------------------------------------------------------
// K2: lp_ext[t,b,s] = acts[t,b, ext[b,s]] - logZ[t,b]
// ---------------------------------------------------------------------------
__global__ __launch_bounds__(256) void gather_kernel(const float* __restrict__ acts,
                                                     const int* __restrict__ targets) {
    int idx = blockIdx.x * 256 + threadIdx.x;      // (t*BB + b)*SS + s
    if (idx >= TT*BB*SS) return;
    int s  = idx % SS;
    int tb = idx / SS;
    int b  = tb % BB;
    int lab = (s & 1) ? __ldg(&targets[b*LL + (s >> 1)]) : 0;
    g_lp[idx] = __ldg(&acts[(size_t)tb * VV + lab]) - g_logZ[tb];
}

// ---------------------------------------------------------------------------
// K3: forward alpha scan, one block per batch sample, thread s = one state
// ---------------------------------------------------------------------------
__global__ __launch_bounds__(256) void scan_kernel(const int* __restrict__ targets,
                                                   const int* __restrict__ act_lens,
                                                   const int* __restrict__ label_lens) {
    const int b = blockIdx.x;
    const int s = threadIdx.x;                      // 0..255, states 0..SS-1 live
    const int alen = act_lens[b];

    __shared__ float alpha[2][SS];

    bool cs = false;                                // can_skip for this state
    if (s < SS && (s & 1)) {
        int cur = targets[b*LL + (s >> 1)];
        int prv = (s >= 3) ? targets[b*LL + ((s - 2) >> 1)] : -1;
        cs = (cur != 0) && (cur != prv);
    }

    // init t = 0
    if (s < SS) {
        float a0 = NEGF;
        if (s == 0) a0 = g_lp[(0*BB + b)*SS + 0];
        if (s == 1) a0 = g_lp[(0*BB + b)*SS + 1];
        alpha[0][s] = a0;
    }
    __syncthreads();

    // prefetch pipeline: 4 time-steps of lp per thread
    float lpA[4], lpB[4];
    #pragma unroll
    for (int j = 0; j < 4; j++) {
        int t = 1 + j;
        lpA[j] = (s < SS && t < TT) ? g_lp[(t*BB + b)*SS + s] : 0.f;
    }

    int cur = 1;                                    // buffer parity for t
    for (int t0 = 1; t0 < TT; t0 += 4) {
        #pragma unroll
        for (int j = 0; j < 4; j++) {
            int tn = t0 + 4 + j;
            lpB[j] = (s < SS && tn < TT) ? g_lp[(tn*BB + b)*SS + s] : 0.f;
        }
        #pragma unroll
        for (int j = 0; j < 4; j++) {
            int t = t0 + j;
            if (t >= TT) break;                     // uniform across block
            int prv = cur ^ 1;
            if (s < SS) {
                float a1 = alpha[prv][s];
                float a2 = (s >= 1) ? alpha[prv][s - 1] : NEGF;
                float a3 = (cs && s >= 2) ? alpha[prv][s - 2] : NEGF;
                float nv = logadd2(a1, logadd2(a2, a3)) + lpA[j];
                alpha[cur][s] = (t < alen) ? nv : a1;
            }
            __syncthreads();
            cur ^= 1;
        }
        #pragma unroll
        for (int j = 0; j < 4; j++) lpA[j] = lpB[j];
    }

    if (s == 0) {
        int fin = cur ^ 1;                          // buffer holding alpha[T-1]
        int sl = 2 * label_lens[b];
        float ll = logadd2(alpha[fin][sl], alpha[fin][sl - 1]);
        g_ps[b] = -ll;
    }
}

// ---------------------------------------------------------------------------
// K4: mean over batch
// ---------------------------------------------------------------------------
__global__ void finalize_kernel(float* __restrict__ out) {
    float v = g_ps[threadIdx.x];                    // 32 threads
    #pragma unroll
    for (int off = 16; off; off >>= 1)
        v += __shfl_xor_sync(0xffffffffu, v, off);
    if (threadIdx.x == 0) out[0] = v / (float)BB;
}

// ---------------------------------------------------------------------------
extern "C" void kernel_launch(void* const* d_in, const int* in_sizes, int n_in,
                              void* d_out, int out_size) {
    const float* acts       = (const float*)d_in[0];
    const int*   targets    = (const int*)d_in[1];
    const int*   act_lens   = (const int*)d_in[2];
    const int*   label_lens = (const int*)d_in[3];
    float* out = (float*)d_out;

    logz_kernel<<<TT*BB, 256>>>(acts);
    int n = TT*BB*SS;
    gather_kernel<<<(n + 255) / 256, 256>>>(acts, targets);
    scan_kernel<<<BB, 256>>>(targets, act_lens, label_lens);
    finalize_kernel<<<1, 32>>>(out);
}

// round 2
// speedup vs baseline: 1.3941x; 1.3941x over previous
#include <cuda_runtime.h>
#include <cuda_bf16.h>

#define TT 512
#define BB 32
#define VV 8000
#define LL 100
#define SS (2*LL+1)   // 201
#define NEGF (-1e30f)

// Scratch (allocation-free rule: __device__ globals)
__device__ float g_lp[TT*BB*SS];      // 13.2 MB

// 3-way logsumexp, MUFU-only fast path.
__device__ __forceinline__ float lse3(float a1, float a2, float a3) {
    float m = fmaxf(a1, fmaxf(a2, a3));
    float r = __expf(a1 - m) + __expf(a2 - m) + __expf(a3 - m);
    return m + __logf(r);
}

// ---------------------------------------------------------------------------
// K1: logZ = logsumexp over V of acts[t,b,:], then gather lp_ext for this row
//     directly (row is L1-resident). One block per (t,b) row.
// ---------------------------------------------------------------------------
__global__ __launch_bounds__(256) void logz_gather_kernel(const float* __restrict__ acts,
                                                          const int* __restrict__ targets,
                                                          float* __restrict__ out) {
    const int row = blockIdx.x;                    // t*BB + b
    const int b   = row % BB;
    const float* __restrict__ rowp = acts + (size_t)row * VV;
    const float4* __restrict__ p = (const float4*)rowp;
    const int tid = threadIdx.x;

    if (row == 0 && tid == 0) out[0] = 0.f;        // zero the batch-mean accumulator

    float m = NEGF, s = 0.f;
    #pragma unroll 4
    for (int i = tid; i < VV/4; i += 256) {
        float4 v = p[i];
        float mx = fmaxf(fmaxf(v.x, v.y), fmaxf(v.z, v.w));
        if (mx > m) { s *= __expf(m - mx); m = mx; }
        s += __expf(v.x - m) + __expf(v.y - m) + __expf(v.z - m) + __expf(v.w - m);
    }
    // warp reduce (m,s)
    #pragma unroll
    for (int off = 16; off; off >>= 1) {
        float m2 = __shfl_xor_sync(0xffffffffu, m, off);
        float s2 = __shfl_xor_sync(0xffffffffu, s, off);
        float M = fmaxf(m, m2);
        s = s * __expf(m - M) + s2 * __expf(m2 - M);
        m = M;
    }
    __shared__ float sm[8], ss[8];
    __shared__ float sLogZ;
    int w = tid >> 5;
    if ((tid & 31) == 0) { sm[w] = m; ss[w] = s; }
    __syncthreads();
    if (tid == 0) {
        float M = sm[0], Sv = ss[0];
        #pragma unroll
        for (int i = 1; i < 8; i++) {
            float m2 = sm[i], s2 = ss[i];
            float Mn = fmaxf(M, m2);
            Sv = Sv * __expf(M - Mn) + s2 * __expf(m2 - Mn);
            M = Mn;
        }
        sLogZ = M + __logf(Sv);
    }
    __syncthreads();

    // Gather the 201 extended-label emissions for this row (L1 hits).
    if (tid < SS) {
        int lab = (tid & 1) ? __ldg(&targets[b*LL + (tid >> 1)]) : 0;
        g_lp[(size_t)row * SS + tid] = rowp[lab] - sLogZ;
    }
}

// ---------------------------------------------------------------------------
// K3: forward alpha scan, one block per batch sample, thread s = one state.
//     224 threads = 7 warps covering 201 states.
// ---------------------------------------------------------------------------
__global__ __launch_bounds__(224) void scan_kernel(const int* __restrict__ targets,
                                                   const int* __restrict__ act_lens,
                                                   const int* __restrict__ label_lens,
                                                   float* __restrict__ out) {
    const int b = blockIdx.x;
    const int s = threadIdx.x;                      // states 0..SS-1 live
    const int alen = act_lens[b];

    __shared__ float alpha[2][SS];

    bool cs = false;                                // can_skip for this state
    if (s < SS && (s & 1)) {
        int cur_lab = targets[b*LL + (s >> 1)];
        int prv_lab = (s >= 3) ? targets[b*LL + ((s - 2) >> 1)] : -1;
        cs = (cur_lab != 0) && (cur_lab != prv_lab);
    }

    // init t = 0
    if (s < SS) {
        float a0 = NEGF;
        if (s <= 1) a0 = g_lp[(size_t)(0*BB + b)*SS + s];
        alpha[0][s] = a0;
    }
    __syncthreads();

    // prefetch pipeline: 4 time-steps of lp per thread
    float lpA[4], lpB[4];
    #pragma unroll
    for (int j = 0; j < 4; j++) {
        int t = 1 + j;
        lpA[j] = (s < SS && t < TT) ? g_lp[(size_t)(t*BB + b)*SS + s] : 0.f;
    }

    int cur = 1;                                    // buffer parity for t
    for (int t0 = 1; t0 < TT; t0 += 4) {
        #pragma unroll
        for (int j = 0; j < 4; j++) {
            int tn = t0 + 4 + j;
            lpB[j] = (s < SS && tn < TT) ? g_lp[(size_t)(tn*BB + b)*SS + s] : 0.f;
        }
        #pragma unroll
        for (int j = 0; j < 4; j++) {
            int t = t0 + j;
            if (t >= TT) break;                     // uniform across block
            int prv = cur ^ 1;
            if (s < SS) {
                float a1 = alpha[prv][s];
                float a2 = (s >= 1) ? alpha[prv][s - 1] : NEGF;
                float a3 = (cs && s >= 2) ? alpha[prv][s - 2] : NEGF;
                float nv = lse3(a1, a2, a3) + lpA[j];
                alpha[cur][s] = (t < alen) ? nv : a1;
            }
            __syncthreads();
            cur ^= 1;
        }
        #pragma unroll
        for (int j = 0; j < 4; j++) lpA[j] = lpB[j];
    }

    if (s == 0) {
        int fin = cur ^ 1;                          // buffer holding alpha[T-1]
        int sl = 2 * label_lens[b];
        float m = fmaxf(alpha[fin][sl], alpha[fin][sl - 1]);
        float ll = m + __logf(__expf(alpha[fin][sl] - m) + __expf(alpha[fin][sl - 1] - m));
        atomicAdd(out, -ll * (1.0f / (float)BB));
    }
}

// ---------------------------------------------------------------------------
extern "C" void kernel_launch(void* const* d_in, const int* in_sizes, int n_in,
                              void* d_out, int out_size) {
    const float* acts       = (const float*)d_in[0];
    const int*   targets    = (const int*)d_in[1];
    const int*   act_lens   = (const int*)d_in[2];
    const int*   label_lens = (const int*)d_in[3];
    float* out = (float*)d_out;

    logz_gather_kernel<<<TT*BB, 256>>>(acts, targets, out);
    scan_kernel<<<BB, 224>>>(targets, act_lens, label_lens, out);
}